// round 14
// baseline (speedup 1.0000x reference)
#include <cuda_runtime.h>
#include <cstdint>

#define ICC 128
#define OCC 128
#define BDIM 64
#define OD  1024
#define LL  2048
#define KC  8            // ic per chunk
#define DT  8            // d per block
#define OT  32           // o per block
#define XROW 66          // float2 per (ic,dd) x-row (64 + 2 pad)
#define WROW 34          // 32 + 2 pad
#define XS_B (KC*DT*XROW*8)          // 33792
#define WS_B (KC*DT*WROW*8)          // 17408
#define BUF_B (XS_B + WS_B)          // 51200
#define SMEM_B (2*BUF_B)             // 102400

using ull = unsigned long long;
#define FMA_F32X2(d_, a_, b_) \
  asm("fma.rn.f32x2 %0, %1, %2, %0;" : "+l"(d_) : "l"(a_), "l"(b_))

#define CP8(dst_, src_) \
  asm volatile("cp.async.ca.shared.global [%0], [%1], 8;" \
               :: "r"(dst_), "l"(src_) : "memory")

__global__ void __launch_bounds__(512, 1)
nolc10(const float* __restrict__ X, const float* __restrict__ W,
       float* __restrict__ out)
{
    extern __shared__ __align__(16) char sm[];
    uint32_t smb;
    asm("{ .reg .u64 t; cvta.to.shared.u64 t, %1; cvt.u32.u64 %0, t; }"
        : "=r"(smb) : "l"(sm));

    const int tid = threadIdx.x;
    const int oc0 = blockIdx.x * OT;
    const int d0  = blockIdx.y * DT;
    const int l0  = d0 * 2;
    const size_t RS = (size_t)ICC * LL;

    // compute map (R11): dg = d, ty = 8 b's of 8, tx = 8 o's of 4
    const int dg = tid >> 6;
    const int ty = (tid >> 3) & 7;
    const int tx = tid & 7;

    // loader map: lanes along l
    const int jj = tid & 3;
    const int rr = tid >> 2;

    ull acc[8][4];
    #pragma unroll
    for (int i = 0; i < 8; ++i)
        #pragma unroll
        for (int j = 0; j < 4; ++j) acc[i][j] = 0ull;

    // async load chunk c into buffer buf (global -> smem, no regs)
    auto LOAD = [&](int c, int buf) {
        const int ic0 = c * KC;
        const uint32_t xs = smb + buf * BUF_B;
        const uint32_t ws = xs + XS_B;
        #pragma unroll
        for (int p = 0; p < 4; ++p) {
            int r = rr + 128 * p, b = r & 63, ic = r >> 6;
            const float* g = X + (size_t)b * RS + (size_t)(ic0 + ic) * LL
                               + l0 + 4 * jj;
            uint32_t d = xs + (uint32_t)(((ic * DT + 2 * jj) * XROW + b) * 8);
            CP8(d, g);
            CP8(d + XROW * 8, g + 2);
        }
        #pragma unroll
        for (int p = 0; p < 2; ++p) {
            int r = rr + 128 * p, o = r & 31, ic = r >> 5;
            const float* g = W + (size_t)(oc0 + o) * RS + (size_t)(ic0 + ic) * LL
                               + l0 + 4 * jj;
            uint32_t d = ws + (uint32_t)(((ic * DT + 2 * jj) * WROW + o) * 8);
            CP8(d, g);
            CP8(d + WROW * 8, g + 2);
        }
        asm volatile("cp.async.commit_group;" ::: "memory");
    };

    LOAD(0, 0);
    asm volatile("cp.async.wait_group 0;" ::: "memory");
    __syncthreads();

    int buf = 0;
    for (int c = 0; c < ICC / KC; ++c) {
        if (c + 1 < ICC / KC) LOAD(c + 1, buf ^ 1);

        const char* xb = sm + buf * BUF_B + (size_t)dg * (XROW * 8) + ty * 64;
        const char* wb = sm + buf * BUF_B + XS_B + (size_t)dg * (WROW * 8) + tx * 32;
        #pragma unroll
        for (int k = 0; k < KC; ++k) {
            const ulonglong2* xp = reinterpret_cast<const ulonglong2*>(
                xb + (size_t)k * (DT * XROW * 8));
            const ulonglong2* wp = reinterpret_cast<const ulonglong2*>(
                wb + (size_t)k * (DT * WROW * 8));
            ulonglong2 w01 = wp[0], w23 = wp[1];
            ull wv[4] = { w01.x, w01.y, w23.x, w23.y };
            ulonglong2 a0 = xp[0], a1 = xp[1], a2 = xp[2], a3 = xp[3];
            ull xv[8] = { a0.x, a0.y, a1.x, a1.y, a2.x, a2.y, a3.x, a3.y };
            #pragma unroll
            for (int bb = 0; bb < 8; ++bb)
                #pragma unroll
                for (int oo = 0; oo < 4; ++oo)
                    FMA_F32X2(acc[bb][oo], xv[bb], wv[oo]);
        }

        if (c + 1 < ICC / KC)
            asm volatile("cp.async.wait_group 0;" ::: "memory");
        __syncthreads();
        buf ^= 1;
    }

    // ---- epilogue through smem: 32B contiguous d-runs out ----
    const float scale = 0.08838834764831843f;  // 1/sqrt(128)
    float* eb = reinterpret_cast<float*>(sm);  // Ebuf[64][32][12]
    #pragma unroll
    for (int bb = 0; bb < 8; ++bb)
        #pragma unroll
        for (int oo = 0; oo < 4; ++oo) {
            float2 v = *reinterpret_cast<float2*>(&acc[bb][oo]);
            eb[((8 * ty + bb) * OT + 4 * tx + oo) * 12 + dg] = (v.x + v.y) * scale;
        }
    __syncthreads();
    #pragma unroll
    for (int i = 0; i < 8; ++i) {
        int s = i * 512 + tid;
        int j = s & 1, row = s >> 1;           // row = b*32 + o
        int b = row >> 5, o = row & 31;
        float4 v = *reinterpret_cast<const float4*>(eb + row * 12 + 4 * j);
        *reinterpret_cast<float4*>(
            out + ((size_t)b * OCC + oc0 + o) * OD + d0 + 4 * j) = v;
    }
}

extern "C" void kernel_launch(void* const* d_in, const int* in_sizes, int n_in,
                              void* d_out, int out_size)
{
    const void* xa = d_in[0];
    const void* wa = d_in[1];
    if (n_in >= 2 && in_sizes[0] == OCC * ICC * LL &&
        in_sizes[1] == BDIM * ICC * LL) {
        const void* t = xa; xa = wa; wa = t;   // defensive: order swapped
    }
    cudaFuncSetAttribute(nolc10, cudaFuncAttributeMaxDynamicSharedMemorySize,
                         SMEM_B);
    dim3 grid(OCC / OT, OD / DT);              // (4, 128), oc fastest
    nolc10<<<grid, 512, SMEM_B>>>(reinterpret_cast<const float*>(xa),
                                  reinterpret_cast<const float*>(wa),
                                  reinterpret_cast<float*>(d_out));
}